// round 8
// baseline (speedup 1.0000x reference)
#include <cuda_runtime.h>
#include <cuda_bf16.h>

#define NB  16
#define NT  512
#define ND  384
#define RPB 64           // output rows (positions) per block
#define F4R (ND / 4)     // 96 float4 per row

// Fused kernel: per-block redundant scan of this batch's 512 durations,
// smem inverse-map scatter for this block's RPB positions, then a flat
// block-coalesced gather-copy with 4-deep load batching.
__global__ __launch_bounds__(256, 6) void lr_fused_kernel(const float* __restrict__ enc,
                                                          const int* __restrict__ dur,
                                                          float* __restrict__ out,
                                                          float* __restrict__ out_tail,
                                                          int has_tail, int max_len,
                                                          int nchunks) {
    __shared__ int s_wsum[8];       // per-warp pair-sum totals
    __shared__ int s_wexcl[8];      // exclusive warp offsets
    __shared__ int s_tok[RPB];      // token index per local position, -1 => zero row

    const int blk   = blockIdx.x;
    const int b     = blk / nchunks;
    const int chunk = blk - b * nchunks;
    const int cs    = chunk * RPB;
    const int ce    = min(cs + RPB, max_len);

    const int tid  = threadIdx.x;
    const int wid  = tid >> 5;
    const int lane = tid & 31;

    // ---- scan: each thread owns tokens 2*tid, 2*tid+1 ----
    const int2 d2 = ((const int2*)(dur + b * NT))[tid];
    int x = d2.x + d2.y;                      // pair sum
    #pragma unroll
    for (int off = 1; off < 32; off <<= 1) {
        int y = __shfl_up_sync(0xffffffffu, x, off);
        if (lane >= off) x += y;
    }
    if (lane == 31) s_wsum[wid] = x;

    // init smem tok to -1 while waiting
    if (tid < RPB) s_tok[tid] = -1;
    __syncthreads();

    if (wid == 0 && lane < 8) {
        int w = s_wsum[lane];
        int v = w;
        #pragma unroll
        for (int off = 1; off < 8; off <<= 1) {
            int y = __shfl_up_sync(0x000000ffu, v, off);
            if (lane >= off) v += y;
        }
        s_wexcl[lane] = v - w;                // exclusive warp offset
        if (lane == 7) s_wsum[0] = v;         // grand total (mel) reused slot
    }
    __syncthreads();

    const int incl1 = s_wexcl[wid] + x;       // cumsum after token 2*tid+1
    const int incl0 = incl1 - d2.y;           // cumsum after token 2*tid
    const int excl0 = incl0 - d2.x;           // before token 2*tid
    const int mel   = s_wsum[0];

    if (has_tail && chunk == 0 && tid == 0) out_tail[b] = (float)mel;

    // ---- scatter inverse map restricted to [cs, ce) ----
    {
        int lo = max(excl0, cs), hi = min(min(incl0, max_len), ce);
        for (int p = lo; p < hi; ++p) s_tok[p - cs] = 2 * tid;
        lo = max(incl0, cs); hi = min(min(incl1, max_len), ce);
        for (int p = lo; p < hi; ++p) s_tok[p - cs] = 2 * tid + 1;
    }
    __syncthreads();

    // ---- flat gather-copy: 64 rows * 96 float4 = 6144 float4 per block ----
    // Thread handles f = g*256 + tid, g in [0, 24). Unroll by 4 for MLP.
    const int cnt4 = (ce - cs) * F4R;
    const float4* __restrict__ base = (const float4*)(enc + (size_t)b * NT * ND);
    float4* __restrict__ dst = (float4*)(out + ((size_t)b * max_len + cs) * ND);

    #pragma unroll
    for (int g = 0; g < RPB * F4R / 256; g += 4) {
        float4 v[4];
        #pragma unroll
        for (int j = 0; j < 4; ++j) {
            const int f = (g + j) * 256 + tid;
            v[j] = make_float4(0.f, 0.f, 0.f, 0.f);
            if (f < cnt4) {
                const int row = f / F4R;          // magic-mul division
                const int tok = s_tok[row];       // LDS, conflict-free
                if (tok >= 0) v[j] = base[tok * F4R + (f - row * F4R)];
            }
        }
        #pragma unroll
        for (int j = 0; j < 4; ++j) {
            const int f = (g + j) * 256 + tid;
            if (f < cnt4) dst[f] = v[j];
        }
    }
}

// Zero-fill residual tail elements beyond the B mel_lens slots (defensive).
__global__ void fill_zero_kernel(float* __restrict__ p, long long n) {
    long long i = (long long)blockIdx.x * blockDim.x + threadIdx.x;
    if (i < n) p[i] = 0.f;
}

extern "C" void kernel_launch(void* const* d_in, const int* in_sizes, int n_in,
                              void* d_out, int out_size) {
    const float* enc = (const float*)d_in[0];
    const int*   dur = (const int*)d_in[1];
    float* out = (float*)d_out;

    // Derive max_len from out_size: out = [B, max_len, D] floats (+ B mel_lens tail).
    const long long row_elems = (long long)NB * ND;   // 6144
    long long total = (long long)out_size;
    int max_len;
    long long tail_elems;
    if (total % row_elems == 0) {
        max_len = (int)(total / row_elems);
        tail_elems = 0;
    } else {
        tail_elems = total % row_elems;                // typically == NB
        max_len = (int)((total - tail_elems) / row_elems);
    }

    const long long body = (long long)NB * max_len * ND;
    float* tail = out + body;

    const int nchunks = (max_len + RPB - 1) / RPB;
    lr_fused_kernel<<<NB * nchunks, 256>>>(enc, dur, out, tail,
                                           tail_elems >= NB ? 1 : 0, max_len, nchunks);

    if (tail_elems > NB) {
        long long rem = tail_elems - NB;
        fill_zero_kernel<<<(int)((rem + 255) / 256), 256>>>(tail + NB, rem);
    }
}

// round 12
// speedup vs baseline: 1.0116x; 1.0116x over previous
#include <cuda_runtime.h>
#include <cuda_bf16.h>
#include <cstdint>

#define NB  16
#define NT  512
#define ND  384
#define RPB 16           // output rows (positions) per block
#define F4R (ND / 4)     // 96 float4 per row
#define CNT4 (RPB * F4R) // 1536 float4 per chunk
#define FPT (CNT4 / 256) // 6 float4 per thread

__device__ __forceinline__ void cp_async16(float4* smem_dst, const float4* gmem_src) {
    unsigned int s = (unsigned int)__cvta_generic_to_shared(smem_dst);
    asm volatile("cp.async.cg.shared.global [%0], [%1], 16;" :: "r"(s), "l"(gmem_src));
}

// Fused kernel: per-block redundant scan of this batch's 512 durations,
// smem inverse-map scatter for this block's 16 positions, then an async
// gather (cp.async) into smem staging and a latency-free smem->gmem drain.
__global__ __launch_bounds__(256, 8) void lr_fused_kernel(const float* __restrict__ enc,
                                                          const int* __restrict__ dur,
                                                          float* __restrict__ out,
                                                          float* __restrict__ out_tail,
                                                          int has_tail, int max_len,
                                                          int nchunks) {
    __shared__ int    s_wsum[8];     // per-warp pair-sum totals
    __shared__ int    s_wexcl[8];    // exclusive warp offsets
    __shared__ int    s_tok[RPB];    // token per local position, -1 => zero row
    __shared__ float4 s_buf[CNT4];   // 24 KB staging

    const int blk   = blockIdx.x;
    const int b     = blk / nchunks;
    const int chunk = blk - b * nchunks;
    const int cs    = chunk * RPB;
    const int ce    = min(cs + RPB, max_len);

    const int tid  = threadIdx.x;
    const int wid  = tid >> 5;
    const int lane = tid & 31;

    // ---- scan: each thread owns tokens 2*tid, 2*tid+1 ----
    const int2 d2 = ((const int2*)(dur + b * NT))[tid];
    int x = d2.x + d2.y;                      // pair sum
    #pragma unroll
    for (int off = 1; off < 32; off <<= 1) {
        int y = __shfl_up_sync(0xffffffffu, x, off);
        if (lane >= off) x += y;
    }
    if (lane == 31) s_wsum[wid] = x;

    if (tid < RPB) s_tok[tid] = -1;           // init while waiting
    __syncthreads();

    if (wid == 0 && lane < 8) {
        int w = s_wsum[lane];
        int v = w;
        #pragma unroll
        for (int off = 1; off < 8; off <<= 1) {
            int y = __shfl_up_sync(0x000000ffu, v, off);
            if (lane >= off) v += y;
        }
        s_wexcl[lane] = v - w;                // exclusive warp offset
        if (lane == 7) s_wsum[0] = v;         // grand total (mel)
    }
    __syncthreads();

    const int incl1 = s_wexcl[wid] + x;       // cumsum after token 2*tid+1
    const int incl0 = incl1 - d2.y;           // cumsum after token 2*tid
    const int excl0 = incl0 - d2.x;           // before token 2*tid
    const int mel   = s_wsum[0];

    if (has_tail && chunk == 0 && tid == 0) out_tail[b] = (float)mel;

    // ---- scatter inverse map restricted to [cs, ce) ----
    {
        int lo = max(excl0, cs), hi = min(min(incl0, max_len), ce);
        for (int p = lo; p < hi; ++p) s_tok[p - cs] = 2 * tid;
        lo = max(incl0, cs); hi = min(min(incl1, max_len), ce);
        for (int p = lo; p < hi; ++p) s_tok[p - cs] = 2 * tid + 1;
    }
    __syncthreads();

    // ---- async gather: each thread cp.asyncs its own FPT slots ----
    const int nf = (ce - cs) * F4R;
    const float4* __restrict__ base = (const float4*)(enc + (size_t)b * NT * ND);
    float4* __restrict__ dst = (float4*)(out + ((size_t)b * max_len + cs) * ND);

    int tokv[FPT];
    #pragma unroll
    for (int j = 0; j < FPT; ++j) {
        const int f = j * 256 + tid;
        const int row = f / F4R;              // magic-mul
        tokv[j] = -1;
        if (f < nf) {
            const int tok = s_tok[row];       // LDS, cheap
            tokv[j] = tok;
            if (tok >= 0)
                cp_async16(&s_buf[f], base + tok * F4R + (f - row * F4R));
        }
    }
    asm volatile("cp.async.commit_group;\n\tcp.async.wait_group 0;" ::: "memory");

    // ---- drain: own slots only -> no __syncthreads needed ----
    #pragma unroll
    for (int j = 0; j < FPT; ++j) {
        const int f = j * 256 + tid;
        if (f < nf) {
            float4 v = make_float4(0.f, 0.f, 0.f, 0.f);
            if (tokv[j] >= 0) v = s_buf[f];
            dst[f] = v;
        }
    }
}

// Zero-fill residual tail elements beyond the B mel_lens slots (defensive).
__global__ void fill_zero_kernel(float* __restrict__ p, long long n) {
    long long i = (long long)blockIdx.x * blockDim.x + threadIdx.x;
    if (i < n) p[i] = 0.f;
}

extern "C" void kernel_launch(void* const* d_in, const int* in_sizes, int n_in,
                              void* d_out, int out_size) {
    const float* enc = (const float*)d_in[0];
    const int*   dur = (const int*)d_in[1];
    float* out = (float*)d_out;

    // Derive max_len from out_size: out = [B, max_len, D] floats (+ B mel_lens tail).
    const long long row_elems = (long long)NB * ND;   // 6144
    long long total = (long long)out_size;
    int max_len;
    long long tail_elems;
    if (total % row_elems == 0) {
        max_len = (int)(total / row_elems);
        tail_elems = 0;
    } else {
        tail_elems = total % row_elems;                // typically == NB
        max_len = (int)((total - tail_elems) / row_elems);
    }

    const long long body = (long long)NB * max_len * ND;
    float* tail = out + body;

    const int nchunks = (max_len + RPB - 1) / RPB;
    lr_fused_kernel<<<NB * nchunks, 256>>>(enc, dur, out, tail,
                                           tail_elems >= NB ? 1 : 0, max_len, nchunks);

    if (tail_elems > NB) {
        long long rem = tail_elems - NB;
        fill_zero_kernel<<<(int)((rem + 255) / 256), 256>>>(tail + NB, rem);
    }
}

// round 13
// speedup vs baseline: 1.0889x; 1.0764x over previous
#include <cuda_runtime.h>
#include <cuda_bf16.h>
#include <cstdint>

#define NB  16
#define NT  512
#define ND  384
#define F4R (ND / 4)     // 96 float4 per row
#define TPB 8            // tokens per block (one per warp)
#define NCH (NT / TPB)   // 64 blocks per batch

// Token-centric fused kernel: per-block redundant scan of the batch's 512
// durations into smem cum[], then each warp owns one token: load its row once,
// store dur copies to consecutive output rows. Zero tail striped across warps.
__global__ __launch_bounds__(256, 8) void lr_token_kernel(const float* __restrict__ enc,
                                                          const int* __restrict__ dur,
                                                          float* __restrict__ out,
                                                          float* __restrict__ out_tail,
                                                          int has_tail, int max_len,
                                                          int nchunks) {
    __shared__ int s_wsum[8];       // per-warp pair-sum totals
    __shared__ int s_wexcl[8];      // exclusive warp offsets
    __shared__ int s_cum[NT];       // inclusive cumsum of durations

    const int blk   = blockIdx.x;
    const int b     = blk / nchunks;
    const int chunk = blk - b * nchunks;

    const int tid  = threadIdx.x;
    const int wid  = tid >> 5;
    const int lane = tid & 31;

    // ---- scan: thread owns tokens 2*tid, 2*tid+1 ----
    const int2 d2 = ((const int2*)(dur + b * NT))[tid];
    int x = d2.x + d2.y;                      // pair sum
    #pragma unroll
    for (int off = 1; off < 32; off <<= 1) {
        int y = __shfl_up_sync(0xffffffffu, x, off);
        if (lane >= off) x += y;
    }
    if (lane == 31) s_wsum[wid] = x;
    __syncthreads();

    if (wid == 0 && lane < 8) {
        int w = s_wsum[lane];
        int v = w;
        #pragma unroll
        for (int off = 1; off < 8; off <<= 1) {
            int y = __shfl_up_sync(0x000000ffu, v, off);
            if (lane >= off) v += y;
        }
        s_wexcl[lane] = v - w;                // exclusive warp offset
    }
    __syncthreads();

    const int incl1 = s_wexcl[wid] + x;       // cumsum after token 2*tid+1
    const int incl0 = incl1 - d2.y;           // cumsum after token 2*tid
    s_cum[2 * tid]     = incl0;
    s_cum[2 * tid + 1] = incl1;
    __syncthreads();

    const int mel = s_cum[NT - 1];
    if (has_tail && chunk == 0 && tid == 0) out_tail[b] = (float)mel;

    const float4* __restrict__ base = (const float4*)(enc + (size_t)b * NT * ND);
    float4* __restrict__ out4 = (float4*)(out + (size_t)b * max_len * ND);

    // ---- valid region: warp owns token tok, writes rows [start, end) ----
    const int tok   = chunk * TPB + wid;
    int start = (tok > 0) ? s_cum[tok - 1] : 0;
    int end   = s_cum[tok];
    start = min(start, max_len);
    end   = min(end, max_len);

    if (start < end) {
        const float4* s0 = base + (size_t)tok * F4R;
        const float4 va = s0[lane];
        const float4 vb = s0[lane + 32];
        const float4 vc = s0[lane + 64];
        float4* d = out4 + (size_t)start * F4R;
        for (int p = start; p < end; ++p, d += F4R) {
            d[lane] = va; d[lane + 32] = vb; d[lane + 64] = vc;
        }
    }

    // ---- zero tail: rows [min(mel,max_len), max_len) striped over 512 warps ----
    const int zstart = min(mel, max_len);
    const int gw = chunk * TPB + wid;         // 0..511 within this batch
    const float4 z = make_float4(0.f, 0.f, 0.f, 0.f);
    for (int r = zstart + gw; r < max_len; r += NT) {
        float4* d = out4 + (size_t)r * F4R;
        d[lane] = z; d[lane + 32] = z; d[lane + 64] = z;
    }
}

// Zero-fill residual tail elements beyond the B mel_lens slots (defensive).
__global__ void fill_zero_kernel(float* __restrict__ p, long long n) {
    long long i = (long long)blockIdx.x * blockDim.x + threadIdx.x;
    if (i < n) p[i] = 0.f;
}

extern "C" void kernel_launch(void* const* d_in, const int* in_sizes, int n_in,
                              void* d_out, int out_size) {
    const float* enc = (const float*)d_in[0];
    const int*   dur = (const int*)d_in[1];
    float* out = (float*)d_out;

    // Derive max_len from out_size: out = [B, max_len, D] floats (+ B mel_lens tail).
    const long long row_elems = (long long)NB * ND;   // 6144
    long long total = (long long)out_size;
    int max_len;
    long long tail_elems;
    if (total % row_elems == 0) {
        max_len = (int)(total / row_elems);
        tail_elems = 0;
    } else {
        tail_elems = total % row_elems;                // typically == NB
        max_len = (int)((total - tail_elems) / row_elems);
    }

    const long long body = (long long)NB * max_len * ND;
    float* tail = out + body;

    lr_token_kernel<<<NB * NCH, 256>>>(enc, dur, out, tail,
                                       tail_elems >= NB ? 1 : 0, max_len, NCH);

    if (tail_elems > NB) {
        long long rem = tail_elems - NB;
        fill_zero_kernel<<<(int)((rem + 255) / 256), 256>>>(tail + NB, rem);
    }
}

// round 16
// speedup vs baseline: 1.1969x; 1.0992x over previous
#include <cuda_runtime.h>
#include <cuda_bf16.h>
#include <cstdint>

#define NB  16
#define NT  512
#define ND  384
#define F4R (ND / 4)     // 96 float4 per row
#define NCH (NT / 8)     // 64 blocks per batch (8 tokens per block, one per warp)

// Token-centric fused kernel: per-block redundant scan of the batch's 512
// durations into smem cum[], then each warp owns one token: load its row once
// (cached — reused), store dur copies with streaming hint (evict-first).
// Zero tail rows striped across all 512 warps of the batch.
__global__ __launch_bounds__(256, 8) void lr_token_kernel(const float* __restrict__ enc,
                                                          const int* __restrict__ dur,
                                                          float* __restrict__ out,
                                                          float* __restrict__ out_tail,
                                                          int has_tail, int max_len,
                                                          int nchunks) {
    __shared__ int s_wsum[8];       // per-warp pair-sum totals
    __shared__ int s_wexcl[8];      // exclusive warp offsets
    __shared__ int s_cum[NT];       // inclusive cumsum of durations

    const int blk   = blockIdx.x;
    const int b     = blk / nchunks;
    const int chunk = blk - b * nchunks;

    const int tid  = threadIdx.x;
    const int wid  = tid >> 5;
    const int lane = tid & 31;

    // ---- scan: thread owns tokens 2*tid, 2*tid+1 ----
    const int2 d2 = ((const int2*)(dur + b * NT))[tid];
    int x = d2.x + d2.y;                      // pair sum
    #pragma unroll
    for (int off = 1; off < 32; off <<= 1) {
        int y = __shfl_up_sync(0xffffffffu, x, off);
        if (lane >= off) x += y;
    }
    if (lane == 31) s_wsum[wid] = x;
    __syncthreads();

    if (wid == 0 && lane < 8) {
        int w = s_wsum[lane];
        int v = w;
        #pragma unroll
        for (int off = 1; off < 8; off <<= 1) {
            int y = __shfl_up_sync(0x000000ffu, v, off);
            if (lane >= off) v += y;
        }
        s_wexcl[lane] = v - w;                // exclusive warp offset
    }
    __syncthreads();

    const int incl1 = s_wexcl[wid] + x;       // cumsum after token 2*tid+1
    const int incl0 = incl1 - d2.y;           // cumsum after token 2*tid
    s_cum[2 * tid]     = incl0;
    s_cum[2 * tid + 1] = incl1;
    __syncthreads();

    const int mel = s_cum[NT - 1];
    if (has_tail && chunk == 0 && tid == 0) out_tail[b] = (float)mel;

    const float4* __restrict__ base = (const float4*)(enc + (size_t)b * NT * ND);
    float4* __restrict__ out4 = (float4*)(out + (size_t)b * max_len * ND);

    // ---- valid region: warp owns token tok, writes rows [start, end) ----
    const int tok   = chunk * 8 + wid;
    int start = (tok > 0) ? s_cum[tok - 1] : 0;
    int end   = s_cum[tok];
    start = min(start, max_len);
    end   = min(end, max_len);

    if (start < end) {
        const float4* s0 = base + (size_t)tok * F4R;
        const float4 va = s0[lane];
        const float4 vb = s0[lane + 32];
        const float4 vc = s0[lane + 64];
        float4* d = out4 + (size_t)start * F4R;
        for (int p = start; p < end; ++p, d += F4R) {
            __stcs(d + lane, va);             // streaming: evict-first dirty lines
            __stcs(d + lane + 32, vb);
            __stcs(d + lane + 64, vc);
        }
    }

    // ---- zero tail: rows [min(mel,max_len), max_len) striped over 512 warps ----
    const int zstart = min(mel, max_len);
    const int gw = chunk * 8 + wid;           // 0..511 within this batch
    const float4 z = make_float4(0.f, 0.f, 0.f, 0.f);
    for (int r = zstart + gw; r < max_len; r += NT) {
        float4* d = out4 + (size_t)r * F4R;
        __stcs(d + lane, z);
        __stcs(d + lane + 32, z);
        __stcs(d + lane + 64, z);
    }
}

// Zero-fill residual tail elements beyond the B mel_lens slots (defensive).
__global__ void fill_zero_kernel(float* __restrict__ p, long long n) {
    long long i = (long long)blockIdx.x * blockDim.x + threadIdx.x;
    if (i < n) p[i] = 0.f;
}

extern "C" void kernel_launch(void* const* d_in, const int* in_sizes, int n_in,
                              void* d_out, int out_size) {
    const float* enc = (const float*)d_in[0];
    const int*   dur = (const int*)d_in[1];
    float* out = (float*)d_out;

    // Derive max_len from out_size: out = [B, max_len, D] floats (+ B mel_lens tail).
    const long long row_elems = (long long)NB * ND;   // 6144
    long long total = (long long)out_size;
    int max_len;
    long long tail_elems;
    if (total % row_elems == 0) {
        max_len = (int)(total / row_elems);
        tail_elems = 0;
    } else {
        tail_elems = total % row_elems;                // typically == NB
        max_len = (int)((total - tail_elems) / row_elems);
    }

    const long long body = (long long)NB * max_len * ND;
    float* tail = out + body;

    lr_token_kernel<<<NB * NCH, 256>>>(enc, dur, out, tail,
                                       tail_elems >= NB ? 1 : 0, max_len, NCH);

    if (tail_elems > NB) {
        long long rem = tail_elems - NB;
        fill_zero_kernel<<<(int)((rem + 255) / 256), 256>>>(tail + NB, rem);
    }
}